// round 2
// baseline (speedup 1.0000x reference)
#include <cuda_runtime.h>

#define N_   4
#define L_   4096
#define H_   8
#define D_   64
#define NH   32
#define EPSF 1e-6f

#define CHUNK 256   // tokens per pass1 CTA
#define SUBT  32    // tokens per smem sub-tile
#define TL    64    // tokens per pass2 CTA

// Scratch (allocation-free rule: device globals)
__device__ float g_KV[NH][D_ * D_];   // [nh][d*64 + m]
__device__ float g_Ksum[NH][D_];

__device__ __forceinline__ float fmap(float x) {
    // elu(x) + 1
    return x > 0.f ? x + 1.f : __expf(x);
}

__global__ void zero_kernel() {
    int idx = blockIdx.x * blockDim.x + threadIdx.x;
    if (idx < NH * D_ * D_) ((float*)g_KV)[idx] = 0.f;
    if (idx < NH * D_)      ((float*)g_Ksum)[idx] = 0.f;
}

// Pass 1: KV[d][m] += fmap(k)[l,d] * v[l,m]; Ksum[d] += fmap(k)[l,d]
__global__ __launch_bounds__(256) void pass1(const float* __restrict__ keys,
                                             const float* __restrict__ values) {
    __shared__ float ks[SUBT][D_];
    __shared__ float vs[SUBT][D_];

    const int nh    = blockIdx.x;          // 0..31
    const int chunk = blockIdx.y;          // 0..15
    const int n = nh >> 3, h = nh & 7;
    const int tid  = threadIdx.x;
    const int dblk = tid >> 4;             // 0..15 -> d rows [dblk*4, dblk*4+3]
    const int mblk = tid & 15;             // 0..15 -> m cols [mblk*4, mblk*4+3]

    const float* kbase = keys   + ((size_t)(n * L_) * H_ + h) * D_;
    const float* vbase = values + ((size_t)(n * L_) * H_ + h) * D_;
    const int l0 = chunk * CHUNK;

    float acc[4][4] = {};
    float ksum[4]   = {};

    for (int sub = 0; sub < CHUNK / SUBT; ++sub) {
        const int lbase = l0 + sub * SUBT;
        // cooperative load: 32 tokens x 64 floats for k and v
        #pragma unroll
        for (int r = 0; r < 2; ++r) {
            int f = r * 256 + tid;
            int t = f >> 4;        // token within sub-tile
            int q = f & 15;        // float4 quad within row
            size_t row = (size_t)(lbase + t) * (H_ * D_);
            float4 kk = ((const float4*)(kbase + row))[q];
            kk.x = fmap(kk.x); kk.y = fmap(kk.y); kk.z = fmap(kk.z); kk.w = fmap(kk.w);
            *(float4*)&ks[t][q * 4] = kk;
            *(float4*)&vs[t][q * 4] = ((const float4*)(vbase + row))[q];
        }
        __syncthreads();

        #pragma unroll 8
        for (int t = 0; t < SUBT; ++t) {
            float4 kk = *(float4*)&ks[t][dblk * 4];
            float4 vv = *(float4*)&vs[t][mblk * 4];
            float kr[4] = {kk.x, kk.y, kk.z, kk.w};
            float vr[4] = {vv.x, vv.y, vv.z, vv.w};
            #pragma unroll
            for (int i = 0; i < 4; ++i) {
                ksum[i] += kr[i];
                #pragma unroll
                for (int j = 0; j < 4; ++j)
                    acc[i][j] += kr[i] * vr[j];
            }
        }
        __syncthreads();
    }

    float* kvout = g_KV[nh];
    #pragma unroll
    for (int i = 0; i < 4; ++i)
        #pragma unroll
        for (int j = 0; j < 4; ++j)
            atomicAdd(&kvout[(dblk * 4 + i) * D_ + mblk * 4 + j], acc[i][j]);

    if (mblk == 0) {
        #pragma unroll
        for (int i = 0; i < 4; ++i)
            atomicAdd(&g_Ksum[nh][dblk * 4 + i], ksum[i]);
    }
}

// Pass 2: out[l][m] = z_l * sum_d fmap(q)[l,d] * KV[d][m]
#define QSTR 68   // padded q_s row stride (floats): 272B keeps float4 alignment, avoids bank conflicts

__global__ __launch_bounds__(256) void pass2(const float* __restrict__ queries,
                                             float* __restrict__ out) {
    __shared__ float kv_s[D_ * D_];      // [d][m]
    __shared__ float q_s[TL * QSTR];     // [l][d], padded
    __shared__ float z_s[TL];
    __shared__ float ks_s[D_];

    const int nh   = blockIdx.x;         // 0..31
    const int tile = blockIdx.y;         // 0..63
    const int n = nh >> 3, h = nh & 7;
    const int tid  = threadIdx.x;
    const int lblk = tid >> 4;           // 0..15 -> tokens [lblk*4, lblk*4+3]
    const int mblk = tid & 15;           // 0..15 -> m cols [mblk*4, mblk*4+3]
    const int l0 = tile * TL;

    // Load KV tile (512KB total scratch -> L2-resident across 2048 CTAs)
    #pragma unroll
    for (int r = 0; r < 4; ++r) {
        int f = r * 256 + tid;
        ((float4*)kv_s)[f] = ((const float4*)g_KV[nh])[f];
    }
    if (tid < D_) ks_s[tid] = g_Ksum[nh][tid];

    // Load + featuremap q into [l][d] (padded stride)
    const float* qbase = queries + ((size_t)(n * L_) * H_ + h) * D_;
    {
        int t    = tid >> 2;             // 0..63
        int quad = tid & 3;              // d offset quad*16
        const float4* src = (const float4*)(qbase + (size_t)(l0 + t) * (H_ * D_)) + quad * 4;
        #pragma unroll
        for (int r = 0; r < 4; ++r) {
            float4 qq = src[r];
            qq.x = fmap(qq.x); qq.y = fmap(qq.y); qq.z = fmap(qq.z); qq.w = fmap(qq.w);
            *(float4*)&q_s[t * QSTR + quad * 16 + r * 4] = qq;
        }
    }
    __syncthreads();

    // Normalizer z per token
    if (tid < TL) {
        float s = 0.f;
        #pragma unroll
        for (int d = 0; d < D_; ++d) s += q_s[tid * QSTR + d] * ks_s[d];
        z_s[tid] = 1.f / (s + EPSF);
    }
    __syncthreads();

    // 64x64x64 GEMM: acc[i][j] = sum_d q[l_i][d] * kv[d][m_j]
    float acc[4][4] = {};
    #pragma unroll 4
    for (int d4 = 0; d4 < 16; ++d4) {
        float qr[4][4];   // [i][k]
        float kr[4][4];   // [k][j]
        #pragma unroll
        for (int i = 0; i < 4; ++i) {
            float4 qv = *(float4*)&q_s[(lblk * 4 + i) * QSTR + d4 * 4];
            qr[i][0] = qv.x; qr[i][1] = qv.y; qr[i][2] = qv.z; qr[i][3] = qv.w;
        }
        #pragma unroll
        for (int k = 0; k < 4; ++k) {
            float4 kv = *(float4*)&kv_s[(d4 * 4 + k) * D_ + mblk * 4];
            kr[k][0] = kv.x; kr[k][1] = kv.y; kr[k][2] = kv.z; kr[k][3] = kv.w;
        }
        #pragma unroll
        for (int i = 0; i < 4; ++i)
            #pragma unroll
            for (int j = 0; j < 4; ++j)
                #pragma unroll
                for (int k = 0; k < 4; ++k)
                    acc[i][j] += qr[i][k] * kr[k][j];
    }

    // Scale by z and store
    #pragma unroll
    for (int i = 0; i < 4; ++i) {
        int l = l0 + lblk * 4 + i;
        float z = z_s[lblk * 4 + i];
        float4 o;
        o.x = acc[i][0] * z;
        o.y = acc[i][1] * z;
        o.z = acc[i][2] * z;
        o.w = acc[i][3] * z;
        float* obase = out + (((size_t)(n * L_) + l) * H_ + h) * D_ + mblk * 4;
        *(float4*)obase = o;
    }
}

extern "C" void kernel_launch(void* const* d_in, const int* in_sizes, int n_in,
                              void* d_out, int out_size) {
    const float* q = (const float*)d_in[0];
    const float* k = (const float*)d_in[1];
    const float* v = (const float*)d_in[2];
    float* out = (float*)d_out;
    (void)in_sizes; (void)n_in; (void)out_size;

    zero_kernel<<<(NH * D_ * D_ + 255) / 256, 256>>>();
    pass1<<<dim3(NH, L_ / CHUNK), 256>>>(k, v);
    pass2<<<dim3(NH, L_ / TL), 256>>>(q, out);
}

// round 4
// speedup vs baseline: 1.2407x; 1.2407x over previous
#include <cuda_runtime.h>
#include <cstdint>

#define N_   4
#define L_   4096
#define H_   8
#define D_   64
#define NH   32
#define EPSF 1e-6f

#define P1_CHUNKS 8
#define P1_LC (L_ / P1_CHUNKS)   // 512 tokens per pass1 CTA
#define P1_T  32                 // tokens per smem tile
#define NPART (P1_CHUNKS * 2)    // 16 partial slots per head

#define TL2 64                   // tokens per pass2 CTA (smem fits 48KB static limit)
#define STR 72                   // padded smem row stride (floats)

// Scratch (allocation-free rule: device globals)
__device__ float g_KVp[NH][NPART][D_ * D_];
__device__ float g_KSp[NH][NPART][D_];
__device__ float g_KV[NH][D_ * D_];
__device__ float g_KS[NH][D_];

__device__ __forceinline__ float fmap(float x) {      // elu(x)+1
    return x > 0.f ? x + 1.f : __expf(x);
}
__device__ __forceinline__ float totf32(float x) {    // round-to-nearest tf32 (truncation would bias by ~2^-10)
    uint32_t u;
    asm("cvt.rna.tf32.f32 %0, %1;" : "=r"(u) : "f"(x));
    return __uint_as_float(u);
}
__device__ __forceinline__ void mma_tf32(float* c,
                                         uint32_t a0, uint32_t a1, uint32_t a2, uint32_t a3,
                                         uint32_t b0, uint32_t b1) {
    asm volatile("mma.sync.aligned.m16n8k8.row.col.f32.tf32.tf32.f32 "
                 "{%0,%1,%2,%3}, {%4,%5,%6,%7}, {%8,%9}, {%0,%1,%2,%3};\n"
                 : "+f"(c[0]), "+f"(c[1]), "+f"(c[2]), "+f"(c[3])
                 : "r"(a0), "r"(a1), "r"(a2), "r"(a3), "r"(b0), "r"(b1));
}

// ───────────────────────── Pass 1: KV[d][m] = Σ_l f(k)[l,d]·v[l,m], Ksum[d] = Σ_l f(k)[l,d]
// Grid (NH, 8), 256 threads. Warp w: token-half = w>>2, d-tile = (w&3)*16, full m=64.
__global__ __launch_bounds__(256) void pass1(const float* __restrict__ keys,
                                             const float* __restrict__ values) {
    __shared__ float ks[P1_T][STR];
    __shared__ float vs[P1_T][STR];

    const int nh = blockIdx.x, chunk = blockIdx.y;
    const int n = nh >> 3, h = nh & 7;
    const int tid = threadIdx.x;
    const int w = tid >> 5, lane = tid & 31;
    const int gid = lane >> 2, tig = lane & 3;
    const int half = w >> 2;
    const int d0   = (w & 3) * 16;
    const int tb   = half * 16;

    const float* kb = keys   + ((size_t)(n * L_) * H_ + h) * D_;
    const float* vb = values + ((size_t)(n * L_) * H_ + h) * D_;
    const int l0 = chunk * P1_LC;

    float acc[8][4] = {};
    float s_lo = 0.f, s_hi = 0.f;

    for (int it = 0; it < P1_LC / P1_T; ++it) {
        const int lb = l0 + it * P1_T;
        #pragma unroll
        for (int r = 0; r < 2; ++r) {
            int f = r * 256 + tid;
            int t = f >> 4, q = f & 15;
            size_t row = (size_t)(lb + t) * (H_ * D_);
            float4 k4 = ((const float4*)(kb + row))[q];
            float4 v4 = ((const float4*)(vb + row))[q];
            k4.x = totf32(fmap(k4.x)); k4.y = totf32(fmap(k4.y));
            k4.z = totf32(fmap(k4.z)); k4.w = totf32(fmap(k4.w));
            v4.x = totf32(v4.x); v4.y = totf32(v4.y);
            v4.z = totf32(v4.z); v4.w = totf32(v4.w);
            *(float4*)&ks[t][q * 4] = k4;
            *(float4*)&vs[t][q * 4] = v4;
        }
        __syncthreads();

        #pragma unroll
        for (int kk = 0; kk < 16; kk += 8) {
            const int lr = tb + kk;
            float a0f = ks[lr + tig    ][d0 + gid    ];
            float a1f = ks[lr + tig    ][d0 + gid + 8];
            float a2f = ks[lr + tig + 4][d0 + gid    ];
            float a3f = ks[lr + tig + 4][d0 + gid + 8];
            s_lo += a0f + a2f;
            s_hi += a1f + a3f;
            uint32_t a0 = __float_as_uint(a0f), a1 = __float_as_uint(a1f);
            uint32_t a2 = __float_as_uint(a2f), a3 = __float_as_uint(a3f);
            #pragma unroll
            for (int j = 0; j < 8; ++j) {
                uint32_t b0 = __float_as_uint(vs[lr + tig    ][j * 8 + gid]);
                uint32_t b1 = __float_as_uint(vs[lr + tig + 4][j * 8 + gid]);
                mma_tf32(acc[j], a0, a1, a2, a3, b0, b1);
            }
        }
        __syncthreads();
    }

    s_lo += __shfl_xor_sync(0xffffffffu, s_lo, 1);
    s_lo += __shfl_xor_sync(0xffffffffu, s_lo, 2);
    s_hi += __shfl_xor_sync(0xffffffffu, s_hi, 1);
    s_hi += __shfl_xor_sync(0xffffffffu, s_hi, 2);

    const int part = chunk * 2 + half;
    if (tig == 0) {
        g_KSp[nh][part][d0 + gid]     = s_lo;
        g_KSp[nh][part][d0 + gid + 8] = s_hi;
    }
    float* kv = g_KVp[nh][part];
    #pragma unroll
    for (int j = 0; j < 8; ++j) {
        int col = j * 8 + tig * 2;
        *(float2*)&kv[(d0 + gid    ) * D_ + col] = make_float2(acc[j][0], acc[j][1]);
        *(float2*)&kv[(d0 + gid + 8) * D_ + col] = make_float2(acc[j][2], acc[j][3]);
    }
}

// ───────────────────────── Reduce: sum 16 partials; pre-convert KV to tf32 for pass2
__global__ __launch_bounds__(256) void reduce_kernel() {
    if (blockIdx.x < 128) {
        int base = blockIdx.x * 256 + threadIdx.x;
        int nh = base >> 10;
        int e  = base & 1023;
        float4 s = make_float4(0.f, 0.f, 0.f, 0.f);
        #pragma unroll
        for (int p = 0; p < NPART; ++p) {
            float4 v = ((const float4*)g_KVp[nh][p])[e];
            s.x += v.x; s.y += v.y; s.z += v.z; s.w += v.w;
        }
        s.x = totf32(s.x); s.y = totf32(s.y); s.z = totf32(s.z); s.w = totf32(s.w);
        ((float4*)g_KV[nh])[e] = s;
    } else {
        for (int i = threadIdx.x; i < NH * D_ / 4; i += 256) {
            int nh = i >> 4;
            int e  = i & 15;
            float4 s = make_float4(0.f, 0.f, 0.f, 0.f);
            #pragma unroll
            for (int p = 0; p < NPART; ++p) {
                float4 v = ((const float4*)g_KSp[nh][p])[e];
                s.x += v.x; s.y += v.y; s.z += v.z; s.w += v.w;
            }
            ((float4*)g_KS[nh])[e] = s;
        }
    }
}

// ───────────────────────── Pass 2: out[l][m] = z_l · Σ_d f(q)[l,d]·KV[d][m]
// Grid (NH, 64), 256 threads. Warp w: rows (w>>1)*16, cols (w&1)*32; k = d = 64.
__global__ __launch_bounds__(256) void pass2(const float* __restrict__ queries,
                                             float* __restrict__ out) {
    __shared__ float kv_s[D_][STR];
    __shared__ float q_s[TL2][STR];
    __shared__ float ks_s[D_];

    const int nh = blockIdx.x, tile = blockIdx.y;
    const int n = nh >> 3, h = nh & 7;
    const int tid = threadIdx.x;
    const int w = tid >> 5, lane = tid & 31;
    const int gid = lane >> 2, tig = lane & 3;
    const int l0 = tile * TL2;

    // KV tile (already tf32): 1024 float4 over 256 threads
    #pragma unroll
    for (int r = 0; r < 4; ++r) {
        int f = r * 256 + tid;
        int dd = f >> 4, q4 = f & 15;
        *(float4*)&kv_s[dd][q4 * 4] = ((const float4*)g_KV[nh])[f];
    }
    if (tid < D_) ks_s[tid] = g_KS[nh][tid];

    // q tile: 64 tokens × 64 floats = 1024 float4
    const float* qb = queries + ((size_t)(n * L_) * H_ + h) * D_;
    #pragma unroll
    for (int r = 0; r < 4; ++r) {
        int f = r * 256 + tid;
        int t = f >> 4, q4 = f & 15;
        float4 q4v = ((const float4*)(qb + (size_t)(l0 + t) * (H_ * D_)))[q4];
        q4v.x = totf32(fmap(q4v.x)); q4v.y = totf32(fmap(q4v.y));
        q4v.z = totf32(fmap(q4v.z)); q4v.w = totf32(fmap(q4v.w));
        *(float4*)&q_s[t][q4 * 4] = q4v;
    }
    __syncthreads();

    const int lb = (w >> 1) * 16;     // row tile
    const int c0 = (w & 1) * 32;      // col half
    float acc[4][4] = {};
    float s_lo = 0.f, s_hi = 0.f;

    #pragma unroll
    for (int kk = 0; kk < D_; kk += 8) {
        float ka = ks_s[kk + tig], kc = ks_s[kk + tig + 4];
        float a0f = q_s[lb + gid    ][kk + tig    ];
        float a1f = q_s[lb + gid + 8][kk + tig    ];
        float a2f = q_s[lb + gid    ][kk + tig + 4];
        float a3f = q_s[lb + gid + 8][kk + tig + 4];
        s_lo += a0f * ka + a2f * kc;
        s_hi += a1f * ka + a3f * kc;
        uint32_t a0 = __float_as_uint(a0f), a1 = __float_as_uint(a1f);
        uint32_t a2 = __float_as_uint(a2f), a3 = __float_as_uint(a3f);
        #pragma unroll
        for (int j = 0; j < 4; ++j) {
            uint32_t b0 = __float_as_uint(kv_s[kk + tig    ][c0 + j * 8 + gid]);
            uint32_t b1 = __float_as_uint(kv_s[kk + tig + 4][c0 + j * 8 + gid]);
            mma_tf32(acc[j], a0, a1, a2, a3, b0, b1);
        }
    }

    s_lo += __shfl_xor_sync(0xffffffffu, s_lo, 1);
    s_lo += __shfl_xor_sync(0xffffffffu, s_lo, 2);
    s_hi += __shfl_xor_sync(0xffffffffu, s_hi, 1);
    s_hi += __shfl_xor_sync(0xffffffffu, s_hi, 2);
    const float z_lo = 1.f / (s_lo + EPSF);
    const float z_hi = 1.f / (s_hi + EPSF);

    float* ob_lo = out + (((size_t)(n * L_) + l0 + lb + gid    ) * H_ + h) * D_ + c0;
    float* ob_hi = out + (((size_t)(n * L_) + l0 + lb + gid + 8) * H_ + h) * D_ + c0;
    #pragma unroll
    for (int j = 0; j < 4; ++j) {
        int col = j * 8 + tig * 2;
        *(float2*)(ob_lo + col) = make_float2(acc[j][0] * z_lo, acc[j][1] * z_lo);
        *(float2*)(ob_hi + col) = make_float2(acc[j][2] * z_hi, acc[j][3] * z_hi);
    }
}

extern "C" void kernel_launch(void* const* d_in, const int* in_sizes, int n_in,
                              void* d_out, int out_size) {
    const float* q = (const float*)d_in[0];
    const float* k = (const float*)d_in[1];
    const float* v = (const float*)d_in[2];
    float* out = (float*)d_out;
    (void)in_sizes; (void)n_in; (void)out_size;

    pass1<<<dim3(NH, P1_CHUNKS), 256>>>(k, v);
    reduce_kernel<<<129, 256>>>();
    pass2<<<dim3(NH, L_ / TL2), 256>>>(q, out);
}

// round 5
// speedup vs baseline: 1.4456x; 1.1651x over previous
#include <cuda_runtime.h>
#include <cstdint>

#define N_   4
#define L_   4096
#define H_   8
#define D_   64
#define NH   32
#define EPSF 1e-6f

#define P1_CHUNKS 32
#define P1_LC (L_ / P1_CHUNKS)   // 128 tokens per pass1 CTA
#define P1_T  32                 // tokens per smem tile
#define NPART P1_CHUNKS          // one partial slot per CTA

#define TL2 128                  // tokens per pass2 CTA (dynamic smem)
#define STR 72                   // padded smem row stride: banks = 8*tig+gid, conflict-free

// Scratch (allocation-free rule: device globals)
__device__ float g_KVp[NH][NPART][D_ * D_];
__device__ float g_KSp[NH][NPART][D_];
__device__ float g_KV[NH][D_ * D_];
__device__ float g_KS[NH][D_];

__device__ __forceinline__ float fmap(float x) {      // elu(x)+1
    return x > 0.f ? x + 1.f : __expf(x);
}
__device__ __forceinline__ float totf32(float x) {    // round-to-nearest tf32
    uint32_t u;
    asm("cvt.rna.tf32.f32 %0, %1;" : "=r"(u) : "f"(x));
    return __uint_as_float(u);
}
__device__ __forceinline__ void mma_tf32(float* c,
                                         uint32_t a0, uint32_t a1, uint32_t a2, uint32_t a3,
                                         uint32_t b0, uint32_t b1) {
    asm volatile("mma.sync.aligned.m16n8k8.row.col.f32.tf32.tf32.f32 "
                 "{%0,%1,%2,%3}, {%4,%5,%6,%7}, {%8,%9}, {%0,%1,%2,%3};\n"
                 : "+f"(c[0]), "+f"(c[1]), "+f"(c[2]), "+f"(c[3])
                 : "r"(a0), "r"(a1), "r"(a2), "r"(a3), "r"(b0), "r"(b1));
}

// ───────────────────────── Pass 1: KV[d][m] = Σ_l f(k)[l,d]·v[l,m], Ksum[d] = Σ_l f(k)[l,d]
// Grid (NH, 32), 256 threads. Warp w: d-tile (w>>1)*16, m-half (w&1)*32, full 32-token k.
__global__ __launch_bounds__(256) void pass1(const float* __restrict__ keys,
                                             const float* __restrict__ values) {
    __shared__ float ks[P1_T][STR];
    __shared__ float vs[P1_T][STR];

    const int nh = blockIdx.x, chunk = blockIdx.y;
    const int n = nh >> 3, h = nh & 7;
    const int tid = threadIdx.x;
    const int w = tid >> 5, lane = tid & 31;
    const int gid = lane >> 2, tig = lane & 3;
    const int d0 = (w >> 1) * 16;
    const int c0 = (w & 1) * 32;

    const float* kb = keys   + ((size_t)(n * L_) * H_ + h) * D_;
    const float* vb = values + ((size_t)(n * L_) * H_ + h) * D_;
    const int l0 = chunk * P1_LC;

    float acc[4][4] = {};
    float s_lo = 0.f, s_hi = 0.f;

    for (int it = 0; it < P1_LC / P1_T; ++it) {
        const int lb = l0 + it * P1_T;
        #pragma unroll
        for (int r = 0; r < 2; ++r) {
            int f = r * 256 + tid;
            int t = f >> 4, q = f & 15;
            size_t row = (size_t)(lb + t) * (H_ * D_);
            float4 k4 = ((const float4*)(kb + row))[q];
            float4 v4 = ((const float4*)(vb + row))[q];
            k4.x = totf32(fmap(k4.x)); k4.y = totf32(fmap(k4.y));
            k4.z = totf32(fmap(k4.z)); k4.w = totf32(fmap(k4.w));
            v4.x = totf32(v4.x); v4.y = totf32(v4.y);
            v4.z = totf32(v4.z); v4.w = totf32(v4.w);
            *(float4*)&ks[t][q * 4] = k4;
            *(float4*)&vs[t][q * 4] = v4;
        }
        __syncthreads();

        #pragma unroll
        for (int kk = 0; kk < P1_T; kk += 8) {
            float a0f = ks[kk + tig    ][d0 + gid    ];
            float a1f = ks[kk + tig    ][d0 + gid + 8];
            float a2f = ks[kk + tig + 4][d0 + gid    ];
            float a3f = ks[kk + tig + 4][d0 + gid + 8];
            s_lo += a0f + a2f;
            s_hi += a1f + a3f;
            uint32_t a0 = __float_as_uint(a0f), a1 = __float_as_uint(a1f);
            uint32_t a2 = __float_as_uint(a2f), a3 = __float_as_uint(a3f);
            #pragma unroll
            for (int j = 0; j < 4; ++j) {
                uint32_t b0 = __float_as_uint(vs[kk + tig    ][c0 + j * 8 + gid]);
                uint32_t b1 = __float_as_uint(vs[kk + tig + 4][c0 + j * 8 + gid]);
                mma_tf32(acc[j], a0, a1, a2, a3, b0, b1);
            }
        }
        __syncthreads();
    }

    s_lo += __shfl_xor_sync(0xffffffffu, s_lo, 1);
    s_lo += __shfl_xor_sync(0xffffffffu, s_lo, 2);
    s_hi += __shfl_xor_sync(0xffffffffu, s_hi, 1);
    s_hi += __shfl_xor_sync(0xffffffffu, s_hi, 2);

    if (c0 == 0 && tig == 0) {
        g_KSp[nh][chunk][d0 + gid]     = s_lo;
        g_KSp[nh][chunk][d0 + gid + 8] = s_hi;
    }
    float* kv = g_KVp[nh][chunk];
    #pragma unroll
    for (int j = 0; j < 4; ++j) {
        int col = c0 + j * 8 + tig * 2;
        *(float2*)&kv[(d0 + gid    ) * D_ + col] = make_float2(acc[j][0], acc[j][1]);
        *(float2*)&kv[(d0 + gid + 8) * D_ + col] = make_float2(acc[j][2], acc[j][3]);
    }
}

// ───────────────────────── Reduce: sum 32 partials; pre-convert KV to tf32 for pass2
__global__ __launch_bounds__(256) void reduce_kernel() {
    if (blockIdx.x < 128) {
        int base = blockIdx.x * 256 + threadIdx.x;   // float4 index into [NH][4096]
        int nh = base >> 10;
        int e  = base & 1023;
        float4 s = make_float4(0.f, 0.f, 0.f, 0.f);
        #pragma unroll 8
        for (int p = 0; p < NPART; ++p) {
            float4 v = ((const float4*)g_KVp[nh][p])[e];
            s.x += v.x; s.y += v.y; s.z += v.z; s.w += v.w;
        }
        s.x = totf32(s.x); s.y = totf32(s.y); s.z = totf32(s.z); s.w = totf32(s.w);
        ((float4*)g_KV[nh])[e] = s;
    } else {
        for (int i = threadIdx.x; i < NH * D_ / 4; i += 256) {
            int nh = i >> 4;
            int e  = i & 15;
            float4 s = make_float4(0.f, 0.f, 0.f, 0.f);
            #pragma unroll 8
            for (int p = 0; p < NPART; ++p) {
                float4 v = ((const float4*)g_KSp[nh][p])[e];
                s.x += v.x; s.y += v.y; s.z += v.z; s.w += v.w;
            }
            ((float4*)g_KS[nh])[e] = s;
        }
    }
}

// ───────────────────────── Pass 2: out[l][m] = z_l · Σ_d f(q)[l,d]·KV[d][m]
// Grid (NH, 32), 512 threads, dynamic smem. Warp w: rows (w>>1)*16, cols (w&1)*32.
struct P2Smem {
    float kv[D_][STR];
    float q[TL2][STR];
    float ks[D_];
};
#define SMEM2 ((int)sizeof(P2Smem))

__global__ __launch_bounds__(512) void pass2(const float* __restrict__ queries,
                                             float* __restrict__ out) {
    extern __shared__ char smraw[];
    P2Smem& sm = *reinterpret_cast<P2Smem*>(smraw);

    const int nh = blockIdx.x, tile = blockIdx.y;
    const int n = nh >> 3, h = nh & 7;
    const int tid = threadIdx.x;
    const int w = tid >> 5, lane = tid & 31;
    const int gid = lane >> 2, tig = lane & 3;
    const int l0 = tile * TL2;

    // KV tile (tf32): 1024 float4 over 512 threads
    #pragma unroll
    for (int r = 0; r < 2; ++r) {
        int f = r * 512 + tid;
        int dd = f >> 4, q4 = f & 15;
        *(float4*)&sm.kv[dd][q4 * 4] = ((const float4*)g_KV[nh])[f];
    }
    if (tid < D_) sm.ks[tid] = g_KS[nh][tid];

    // q tile: 128 tokens × 64 floats = 2048 float4
    const float* qb = queries + ((size_t)(n * L_) * H_ + h) * D_;
    #pragma unroll
    for (int r = 0; r < 4; ++r) {
        int f = r * 512 + tid;
        int t = f >> 4, q4 = f & 15;
        float4 q4v = ((const float4*)(qb + (size_t)(l0 + t) * (H_ * D_)))[q4];
        q4v.x = totf32(fmap(q4v.x)); q4v.y = totf32(fmap(q4v.y));
        q4v.z = totf32(fmap(q4v.z)); q4v.w = totf32(fmap(q4v.w));
        *(float4*)&sm.q[t][q4 * 4] = q4v;
    }
    __syncthreads();

    const int lb = (w >> 1) * 16;     // row tile (0..7)*16
    const int c0 = (w & 1) * 32;      // col half
    float acc[4][4] = {};
    float s_lo = 0.f, s_hi = 0.f;

    #pragma unroll
    for (int kk = 0; kk < D_; kk += 8) {
        float ka = sm.ks[kk + tig], kc = sm.ks[kk + tig + 4];
        float a0f = sm.q[lb + gid    ][kk + tig    ];
        float a1f = sm.q[lb + gid + 8][kk + tig    ];
        float a2f = sm.q[lb + gid    ][kk + tig + 4];
        float a3f = sm.q[lb + gid + 8][kk + tig + 4];
        s_lo += a0f * ka + a2f * kc;
        s_hi += a1f * ka + a3f * kc;
        uint32_t a0 = __float_as_uint(a0f), a1 = __float_as_uint(a1f);
        uint32_t a2 = __float_as_uint(a2f), a3 = __float_as_uint(a3f);
        #pragma unroll
        for (int j = 0; j < 4; ++j) {
            uint32_t b0 = __float_as_uint(sm.kv[kk + tig    ][c0 + j * 8 + gid]);
            uint32_t b1 = __float_as_uint(sm.kv[kk + tig + 4][c0 + j * 8 + gid]);
            mma_tf32(acc[j], a0, a1, a2, a3, b0, b1);
        }
    }

    s_lo += __shfl_xor_sync(0xffffffffu, s_lo, 1);
    s_lo += __shfl_xor_sync(0xffffffffu, s_lo, 2);
    s_hi += __shfl_xor_sync(0xffffffffu, s_hi, 1);
    s_hi += __shfl_xor_sync(0xffffffffu, s_hi, 2);
    const float z_lo = 1.f / (s_lo + EPSF);
    const float z_hi = 1.f / (s_hi + EPSF);

    float* ob_lo = out + (((size_t)(n * L_) + l0 + lb + gid    ) * H_ + h) * D_ + c0;
    float* ob_hi = out + (((size_t)(n * L_) + l0 + lb + gid + 8) * H_ + h) * D_ + c0;
    #pragma unroll
    for (int j = 0; j < 4; ++j) {
        int col = j * 8 + tig * 2;
        *(float2*)(ob_lo + col) = make_float2(acc[j][0] * z_lo, acc[j][1] * z_lo);
        *(float2*)(ob_hi + col) = make_float2(acc[j][2] * z_hi, acc[j][3] * z_hi);
    }
}

extern "C" void kernel_launch(void* const* d_in, const int* in_sizes, int n_in,
                              void* d_out, int out_size) {
    const float* q = (const float*)d_in[0];
    const float* k = (const float*)d_in[1];
    const float* v = (const float*)d_in[2];
    float* out = (float*)d_out;
    (void)in_sizes; (void)n_in; (void)out_size;

    // Idempotent, not a stream op — safe under graph capture.
    cudaFuncSetAttribute(pass2, cudaFuncAttributeMaxDynamicSharedMemorySize, SMEM2);

    pass1<<<dim3(NH, P1_CHUNKS), 256>>>(k, v);
    reduce_kernel<<<129, 256>>>();
    pass2<<<dim3(NH, L_ / TL2), 512, SMEM2>>>(q, out);
}

// round 6
// speedup vs baseline: 1.6586x; 1.1474x over previous
#include <cuda_runtime.h>
#include <cstdint>

#define N_   4
#define L_   4096
#define H_   8
#define D_   64
#define NH   32
#define EPSF 1e-6f

#define P1_CHUNKS 32
#define P1_LC (L_ / P1_CHUNKS)   // 128 tokens per pass1 CTA
#define P1_T  32                 // tokens per smem tile
#define P1_NT (P1_LC / P1_T)     // 4 tiles, 2-stage cp.async pipeline
#define NPART P1_CHUNKS

#define TL2 128                  // tokens per pass2 CTA
#define STR 68                   // padded row stride: 16B-aligned rows, bank = 4*tig+gid (conflict-free)

// Scratch (allocation-free rule: device globals)
__device__ float g_KVp[NH][NPART][D_ * D_];
__device__ float g_KSp[NH][NPART][D_];
__device__ float g_KV[NH][D_ * D_];
__device__ float g_KS[NH][D_];

__device__ __forceinline__ float fmap(float x) {      // elu(x)+1
    return x > 0.f ? x + 1.f : __expf(x);
}
__device__ __forceinline__ float totf32(float x) {    // round-to-nearest tf32
    uint32_t u;
    asm("cvt.rna.tf32.f32 %0, %1;" : "=r"(u) : "f"(x));
    return __uint_as_float(u);
}
__device__ __forceinline__ float ffrag(float x) { return totf32(fmap(x)); }

__device__ __forceinline__ void cp16(void* smem_dst, const void* gmem_src) {
    uint32_t d = (uint32_t)__cvta_generic_to_shared(smem_dst);
    asm volatile("cp.async.cg.shared.global [%0], [%1], 16;\n" :: "r"(d), "l"(gmem_src));
}
__device__ __forceinline__ void cp_commit() {
    asm volatile("cp.async.commit_group;\n");
}
template <int N>
__device__ __forceinline__ void cp_wait() {
    asm volatile("cp.async.wait_group %0;\n" :: "n"(N));
}

__device__ __forceinline__ void mma_tf32(float* c,
                                         uint32_t a0, uint32_t a1, uint32_t a2, uint32_t a3,
                                         uint32_t b0, uint32_t b1) {
    asm volatile("mma.sync.aligned.m16n8k8.row.col.f32.tf32.tf32.f32 "
                 "{%0,%1,%2,%3}, {%4,%5,%6,%7}, {%8,%9}, {%0,%1,%2,%3};\n"
                 : "+f"(c[0]), "+f"(c[1]), "+f"(c[2]), "+f"(c[3])
                 : "r"(a0), "r"(a1), "r"(a2), "r"(a3), "r"(b0), "r"(b1));
}

// ───────────────────────── Pass 1: KV[d][m] = Σ_l f(k)[l,d]·v[l,m], Ksum[d] = Σ_l f(k)[l,d]
// Grid (NH, 32), 256 threads. Warp w: d-tile (w>>1)*16, m-half (w&1)*32.
// Raw tiles stream in via 2-deep cp.async; fmap/rna applied at fragment-read time.
struct P1Smem {
    float ks[2][P1_T][STR];
    float vs[2][P1_T][STR];
};
#define SMEM1 ((int)sizeof(P1Smem))

__global__ __launch_bounds__(256) void pass1(const float* __restrict__ keys,
                                             const float* __restrict__ values) {
    extern __shared__ char smraw[];
    P1Smem& sm = *reinterpret_cast<P1Smem*>(smraw);

    const int nh = blockIdx.x, chunk = blockIdx.y;
    const int n = nh >> 3, h = nh & 7;
    const int tid = threadIdx.x;
    const int w = tid >> 5, lane = tid & 31;
    const int gid = lane >> 2, tig = lane & 3;
    const int d0 = (w >> 1) * 16;
    const int c0 = (w & 1) * 32;

    const float* kb = keys   + ((size_t)(n * L_) * H_ + h) * D_;
    const float* vb = values + ((size_t)(n * L_) * H_ + h) * D_;
    const int l0 = chunk * P1_LC;

    // per-thread load mapping (2 x 16B per array per tile)
    const int t0 = tid >> 4, q40 = tid & 15;            // r=0
    const int t1 = (256 + tid) >> 4, q41 = tid & 15;    // r=1 (t1 = t0+16)

    auto issue = [&](int it) {
        const int b = it & 1;
        const int lb = l0 + it * P1_T;
        cp16(&sm.ks[b][t0][q40 * 4], kb + (size_t)(lb + t0) * (H_ * D_) + q40 * 4);
        cp16(&sm.vs[b][t0][q40 * 4], vb + (size_t)(lb + t0) * (H_ * D_) + q40 * 4);
        cp16(&sm.ks[b][t1][q41 * 4], kb + (size_t)(lb + t1) * (H_ * D_) + q41 * 4);
        cp16(&sm.vs[b][t1][q41 * 4], vb + (size_t)(lb + t1) * (H_ * D_) + q41 * 4);
        cp_commit();
    };

    float acc[4][4] = {};
    float s_lo = 0.f, s_hi = 0.f;

    issue(0);
    #pragma unroll
    for (int it = 0; it < P1_NT; ++it) {
        if (it + 1 < P1_NT) { issue(it + 1); cp_wait<1>(); }
        else                { cp_wait<0>(); }
        __syncthreads();

        const float (*ksb)[STR] = sm.ks[it & 1];
        const float (*vsb)[STR] = sm.vs[it & 1];

        #pragma unroll
        for (int kk = 0; kk < P1_T; kk += 8) {
            float a0f = ffrag(ksb[kk + tig    ][d0 + gid    ]);
            float a1f = ffrag(ksb[kk + tig    ][d0 + gid + 8]);
            float a2f = ffrag(ksb[kk + tig + 4][d0 + gid    ]);
            float a3f = ffrag(ksb[kk + tig + 4][d0 + gid + 8]);
            s_lo += a0f + a2f;
            s_hi += a1f + a3f;
            uint32_t a0 = __float_as_uint(a0f), a1 = __float_as_uint(a1f);
            uint32_t a2 = __float_as_uint(a2f), a3 = __float_as_uint(a3f);
            #pragma unroll
            for (int j = 0; j < 4; ++j) {
                uint32_t b0 = __float_as_uint(totf32(vsb[kk + tig    ][c0 + j * 8 + gid]));
                uint32_t b1 = __float_as_uint(totf32(vsb[kk + tig + 4][c0 + j * 8 + gid]));
                mma_tf32(acc[j], a0, a1, a2, a3, b0, b1);
            }
        }
        __syncthreads();
    }

    s_lo += __shfl_xor_sync(0xffffffffu, s_lo, 1);
    s_lo += __shfl_xor_sync(0xffffffffu, s_lo, 2);
    s_hi += __shfl_xor_sync(0xffffffffu, s_hi, 1);
    s_hi += __shfl_xor_sync(0xffffffffu, s_hi, 2);

    if (c0 == 0 && tig == 0) {
        g_KSp[nh][chunk][d0 + gid]     = s_lo;   // Ksum fmapped twice? no: only this c0==0 warp's values stored once
        g_KSp[nh][chunk][d0 + gid + 8] = s_hi;
    }
    float* kv = g_KVp[nh][chunk];
    #pragma unroll
    for (int j = 0; j < 4; ++j) {
        int col = c0 + j * 8 + tig * 2;
        *(float2*)&kv[(d0 + gid    ) * D_ + col] = make_float2(acc[j][0], acc[j][1]);
        *(float2*)&kv[(d0 + gid + 8) * D_ + col] = make_float2(acc[j][2], acc[j][3]);
    }
}

// ───────────────────────── Reduce: sum 32 partials; pre-convert KV to tf32 for pass2
__global__ __launch_bounds__(256) void reduce_kernel() {
    if (blockIdx.x < 128) {
        int base = blockIdx.x * 256 + threadIdx.x;   // float4 index into [NH][4096]
        int nh = base >> 10;
        int e  = base & 1023;
        float4 s = make_float4(0.f, 0.f, 0.f, 0.f);
        #pragma unroll 8
        for (int p = 0; p < NPART; ++p) {
            float4 v = ((const float4*)g_KVp[nh][p])[e];
            s.x += v.x; s.y += v.y; s.z += v.z; s.w += v.w;
        }
        s.x = totf32(s.x); s.y = totf32(s.y); s.z = totf32(s.z); s.w = totf32(s.w);
        ((float4*)g_KV[nh])[e] = s;
    } else {
        for (int i = threadIdx.x; i < NH * D_ / 4; i += 256) {
            int nh = i >> 4;
            int e  = i & 15;
            float4 s = make_float4(0.f, 0.f, 0.f, 0.f);
            #pragma unroll 8
            for (int p = 0; p < NPART; ++p) {
                float4 v = ((const float4*)g_KSp[nh][p])[e];
                s.x += v.x; s.y += v.y; s.z += v.z; s.w += v.w;
            }
            ((float4*)g_KS[nh])[e] = s;
        }
    }
}

// ───────────────────────── Pass 2: out[l][m] = z_l · Σ_d f(q)[l,d]·KV[d][m]
// Grid (NH, 32), 512 threads. All loads via one cp.async burst (KV already tf32,
// q raw with fmap at fragment read). 52.5KB smem -> 4 CTAs/SM = full occupancy.
struct P2Smem {
    float kv[D_][STR];
    float q[TL2][STR];
    float ks[D_];
};
#define SMEM2 ((int)sizeof(P2Smem))

__global__ __launch_bounds__(512) void pass2(const float* __restrict__ queries,
                                             float* __restrict__ out) {
    extern __shared__ char smraw[];
    P2Smem& sm = *reinterpret_cast<P2Smem*>(smraw);

    const int nh = blockIdx.x, tile = blockIdx.y;
    const int n = nh >> 3, h = nh & 7;
    const int tid = threadIdx.x;
    const int w = tid >> 5, lane = tid & 31;
    const int gid = lane >> 2, tig = lane & 3;
    const int l0 = tile * TL2;

    // q tile first (DRAM, longest latency): 2048 16B chunks over 512 threads
    const float* qb = queries + ((size_t)(n * L_) * H_ + h) * D_;
    #pragma unroll
    for (int r = 0; r < 4; ++r) {
        int f = r * 512 + tid;
        int t = f >> 4, q4 = f & 15;
        cp16(&sm.q[t][q4 * 4], qb + (size_t)(l0 + t) * (H_ * D_) + q4 * 4);
    }
    // KV tile (L2-resident scratch): 1024 chunks
    #pragma unroll
    for (int r = 0; r < 2; ++r) {
        int f = r * 512 + tid;
        int dd = f >> 4, q4 = f & 15;
        cp16(&sm.kv[dd][q4 * 4], (const char*)g_KV[nh] + (size_t)f * 16);
    }
    if (tid < D_) sm.ks[tid] = g_KS[nh][tid];
    cp_commit();
    cp_wait<0>();
    __syncthreads();

    const int lb = (w >> 1) * 16;
    const int c0 = (w & 1) * 32;
    float acc[4][4] = {};
    float s_lo = 0.f, s_hi = 0.f;

    #pragma unroll
    for (int kk = 0; kk < D_; kk += 8) {
        float ka = sm.ks[kk + tig], kc = sm.ks[kk + tig + 4];
        float a0f = ffrag(sm.q[lb + gid    ][kk + tig    ]);
        float a1f = ffrag(sm.q[lb + gid + 8][kk + tig    ]);
        float a2f = ffrag(sm.q[lb + gid    ][kk + tig + 4]);
        float a3f = ffrag(sm.q[lb + gid + 8][kk + tig + 4]);
        s_lo += a0f * ka + a2f * kc;
        s_hi += a1f * ka + a3f * kc;
        uint32_t a0 = __float_as_uint(a0f), a1 = __float_as_uint(a1f);
        uint32_t a2 = __float_as_uint(a2f), a3 = __float_as_uint(a3f);
        #pragma unroll
        for (int j = 0; j < 4; ++j) {
            uint32_t b0 = __float_as_uint(sm.kv[kk + tig    ][c0 + j * 8 + gid]);
            uint32_t b1 = __float_as_uint(sm.kv[kk + tig + 4][c0 + j * 8 + gid]);
            mma_tf32(acc[j], a0, a1, a2, a3, b0, b1);
        }
    }

    s_lo += __shfl_xor_sync(0xffffffffu, s_lo, 1);
    s_lo += __shfl_xor_sync(0xffffffffu, s_lo, 2);
    s_hi += __shfl_xor_sync(0xffffffffu, s_hi, 1);
    s_hi += __shfl_xor_sync(0xffffffffu, s_hi, 2);
    const float z_lo = 1.f / (s_lo + EPSF);
    const float z_hi = 1.f / (s_hi + EPSF);

    float* ob_lo = out + (((size_t)(n * L_) + l0 + lb + gid    ) * H_ + h) * D_ + c0;
    float* ob_hi = out + (((size_t)(n * L_) + l0 + lb + gid + 8) * H_ + h) * D_ + c0;
    #pragma unroll
    for (int j = 0; j < 4; ++j) {
        int col = j * 8 + tig * 2;
        *(float2*)(ob_lo + col) = make_float2(acc[j][0] * z_lo, acc[j][1] * z_lo);
        *(float2*)(ob_hi + col) = make_float2(acc[j][2] * z_hi, acc[j][3] * z_hi);
    }
}

extern "C" void kernel_launch(void* const* d_in, const int* in_sizes, int n_in,
                              void* d_out, int out_size) {
    const float* q = (const float*)d_in[0];
    const float* k = (const float*)d_in[1];
    const float* v = (const float*)d_in[2];
    float* out = (float*)d_out;
    (void)in_sizes; (void)n_in; (void)out_size;

    // Idempotent, not stream ops — safe under graph capture.
    cudaFuncSetAttribute(pass1, cudaFuncAttributeMaxDynamicSharedMemorySize, SMEM1);
    cudaFuncSetAttribute(pass2, cudaFuncAttributeMaxDynamicSharedMemorySize, SMEM2);

    pass1<<<dim3(NH, P1_CHUNKS), 256, SMEM1>>>(k, v);
    reduce_kernel<<<129, 256>>>();
    pass2<<<dim3(NH, L_ / TL2), 512, SMEM2>>>(q, out);
}